// round 11
// baseline (speedup 1.0000x reference)
#include <cuda_runtime.h>
#include <cmath>

#define BB 128
#define LL 512
#define HH 512
#define TT 24
#define TAG_START 22
#define TAG_STOP  23
#define SEG 32
#define SS  16            // steps per segment = LL/SEG

// Scratch (device globals; no allocations).
__device__ float g_X[BB * LL * TT];          // exp(emissions)  6.3 MB
__device__ float g_P[BB * SEG * 576];        // segment transport matrices 9.4 MB
__device__ int   g_M[BB * SEG];              // segment exponent offsets

// m16n8k8 tf32 mma (seg_kernel)
#define MMA_TF32(c0,c1,c2,c3,a0,a1,a2,a3,b0,b1) \
  asm("mma.sync.aligned.m16n8k8.row.col.f32.tf32.tf32.f32 " \
      "{%0,%1,%2,%3},{%4,%5,%6,%7},{%8,%9},{%0,%1,%2,%3};" \
      : "+f"(c0),"+f"(c1),"+f"(c2),"+f"(c3) \
      : "r"(a0),"r"(a1),"r"(a2),"r"(a3),"r"(b0),"r"(b1))

// m16n8k16 bf16 mma (emit kernel)
#define MMA_BF16(c0,c1,c2,c3,a0,a1,a2,a3,b0,b1) \
  asm("mma.sync.aligned.m16n8k16.row.col.f32.bf16.bf16.f32 " \
      "{%0,%1,%2,%3},{%4,%5,%6,%7},{%8,%9},{%0,%1,%2,%3};" \
      : "+f"(c0),"+f"(c1),"+f"(c2),"+f"(c3) \
      : "r"(a0),"r"(a1),"r"(a2),"r"(a3),"r"(b0),"r"(b1))

__device__ __forceinline__ unsigned f2tf32(float v) {
    unsigned r;
    asm("cvt.rna.tf32.f32 %0, %1;" : "=r"(r) : "f"(v));
    return r;
}

// pack two floats into bf16x2: low half = lo (smaller k), high half = hi
__device__ __forceinline__ unsigned pk_bf16x2(float lo, float hi) {
    unsigned r;
    asm("cvt.rn.bf16x2.f32 %0, %1, %2;" : "=r"(r) : "f"(hi), "f"(lo));
    return r;
}

// ---------------------------------------------------------------------------
// Kernel 1: emission GEMM + exp via bf16 m16n8k16 tensor cores.
// Double-buffered A tile (one __syncthreads per chunk) + 3 CTAs/SM.
// CTA: 256 thr / 8 warps / 128 rows.  K pipelined in 8 chunks of 64.
// ---------------------------------------------------------------------------
#define SA 72     // A-tile row stride in bf16 units (64 used + 8 pad)
#define SK 520    // Wtn row stride in bf16 units (512 used + 8 pad)

__global__ void __launch_bounds__(256, 3) emit_kernel(
    const float* __restrict__ feat,
    const float* __restrict__ Wm,
    const float* __restrict__ bias)
{
    __shared__ unsigned short Wtn[TT * SK];      // 24.4 KB  bf16 W^T as [n][k]
    __shared__ unsigned short Asm[2][128 * SA];  // 36.0 KB  bf16 A double buffer

    const int tid = threadIdx.x;

    // Stage Wtn[n][k] = bf16(Wm[n*512 + k])
    for (int idx = tid; idx < TT * (HH / 4); idx += 256) {
        const int n  = idx >> 7;
        const int kq = idx & 127;
        const float4 wv = *reinterpret_cast<const float4*>(Wm + n * HH + kq * 4);
        uint2 p;
        p.x = pk_bf16x2(wv.x, wv.y);
        p.y = pk_bf16x2(wv.z, wv.w);
        *reinterpret_cast<uint2*>(&Wtn[n * SK + kq * 4]) = p;
    }

    // A staging mapping: thread -> (rowb = tid>>4, col4 = tid&15)
    const int col4 = tid & 15;
    const int rowb = tid >> 4;
    const long rowCTA = (long)blockIdx.x * 128;
    const float* gbase = feat + (rowCTA + rowb) * HH + col4 * 4;

    const int warp = tid >> 5;
    const int lane = tid & 31;
    const int g = lane >> 2;
    const int q = lane & 3;
    const int r0 = warp * 16 + g;

    float c0[3], c1[3], c2[3], c3[3];
    #pragma unroll
    for (int nt = 0; nt < 3; ++nt) { c0[nt]=0.f; c1[nt]=0.f; c2[nt]=0.f; c3[nt]=0.f; }

    // preload + store chunk 0 into buffer 0
    float4 fr[8];
    #pragma unroll
    for (int i = 0; i < 8; ++i)
        fr[i] = *reinterpret_cast<const float4*>(gbase + (long)i * 16 * HH);
    #pragma unroll
    for (int i = 0; i < 8; ++i) {
        uint2 p;
        p.x = pk_bf16x2(fr[i].x, fr[i].y);
        p.y = pk_bf16x2(fr[i].z, fr[i].w);
        *reinterpret_cast<uint2*>(&Asm[0][(rowb + 16 * i) * SA + col4 * 4]) = p;
    }
    __syncthreads();   // covers W staging + chunk 0

    for (int c = 0; c < 8; ++c) {
        const int pb = c & 1;

        // issue LDGs for chunk c+1 (latency hidden under this chunk's mma)
        if (c < 7) {
            #pragma unroll
            for (int i = 0; i < 8; ++i)
                fr[i] = *reinterpret_cast<const float4*>(
                    gbase + (c + 1) * 64 + (long)i * 16 * HH);
        }

        // 4 k16 iterations over this chunk
        #pragma unroll
        for (int kk = 0; kk < 4; ++kk) {
            const int kl = kk * 16;
            const unsigned a0 = *reinterpret_cast<const unsigned*>(
                &Asm[pb][r0 * SA + kl + 2 * q]);
            const unsigned a1 = *reinterpret_cast<const unsigned*>(
                &Asm[pb][(r0 + 8) * SA + kl + 2 * q]);
            const unsigned a2 = *reinterpret_cast<const unsigned*>(
                &Asm[pb][r0 * SA + kl + 8 + 2 * q]);
            const unsigned a3 = *reinterpret_cast<const unsigned*>(
                &Asm[pb][(r0 + 8) * SA + kl + 8 + 2 * q]);

            const int kg = c * 64 + kl;
            #pragma unroll
            for (int nt = 0; nt < 3; ++nt) {
                const int n = 8 * nt + g;
                const unsigned b0 = *reinterpret_cast<const unsigned*>(
                    &Wtn[n * SK + kg + 2 * q]);
                const unsigned b1 = *reinterpret_cast<const unsigned*>(
                    &Wtn[n * SK + kg + 8 + 2 * q]);
                MMA_BF16(c0[nt], c1[nt], c2[nt], c3[nt],
                         a0, a1, a2, a3, b0, b1);
            }
        }

        // store chunk c+1 into the other buffer; sync orders it for next iter
        if (c < 7) {
            #pragma unroll
            for (int i = 0; i < 8; ++i) {
                uint2 p;
                p.x = pk_bf16x2(fr[i].x, fr[i].y);
                p.y = pk_bf16x2(fr[i].z, fr[i].w);
                *reinterpret_cast<uint2*>(
                    &Asm[1 - pb][(rowb + 16 * i) * SA + col4 * 4]) = p;
            }
            __syncthreads();
        }
    }

    // epilogue: add bias, exp, store pairs
    const long rg = rowCTA + r0;
    #pragma unroll
    for (int nt = 0; nt < 3; ++nt) {
        const int col = nt * 8 + 2 * q;
        const float bv0 = __ldg(bias + col);
        const float bv1 = __ldg(bias + col + 1);
        float2 lo = make_float2(__expf(c0[nt] + bv0), __expf(c1[nt] + bv1));
        float2 hi = make_float2(__expf(c2[nt] + bv0), __expf(c3[nt] + bv1));
        *reinterpret_cast<float2*>(g_X + rg * TT + col)       = lo;
        *reinterpret_cast<float2*>(g_X + (rg + 8) * TT + col) = hi;
    }
}

// ---------------------------------------------------------------------------
// Kernel 2 (Phase A): per-segment transport matrices via chained tf32 mma.
// SEG=32 segments of SS=16 steps: same total mma work, 2x warps (4096),
// half the per-warp serial chain.
// ---------------------------------------------------------------------------
__global__ __launch_bounds__(128) void seg_kernel(
    const float* __restrict__ trans,
    const int*   __restrict__ lengths)
{
    __shared__ float Psm[4][2][24 * 28];
    __shared__ float xsm[4][SS * TT];

    const int lane = threadIdx.x & 31;
    const int wid  = threadIdx.x >> 5;
    const int idx  = blockIdx.x * 4 + wid;   // 0..4095
    const int b = idx >> 5;
    const int g = idx & 31;

    const int gr = lane >> 2;
    const int qt = lane & 3;

    unsigned A[2][3][4];
    #pragma unroll
    for (int m = 0; m < 2; ++m) {
        const int r0 = 16 * m + gr;
        const int r1 = r0 + 8;
        #pragma unroll
        for (int ks = 0; ks < 3; ++ks) {
            const int c0 = 8 * ks + qt;
            const int c1 = c0 + 4;
            A[m][ks][0] = (r0 < TT) ? f2tf32(__expf(trans[r0 * TT + c0])) : 0u;
            A[m][ks][1] = (r1 < TT) ? f2tf32(__expf(trans[r1 * TT + c0])) : 0u;
            A[m][ks][2] = (r0 < TT) ? f2tf32(__expf(trans[r0 * TT + c1])) : 0u;
            A[m][ks][3] = (r1 < TT) ? f2tf32(__expf(trans[r1 * TT + c1])) : 0u;
        }
    }

    float C[2][3][4];
    #pragma unroll
    for (int m = 0; m < 2; ++m) {
        const int r0 = 16 * m + gr;
        const int r1 = r0 + 8;
        #pragma unroll
        for (int nt = 0; nt < 3; ++nt) {
            const int col0 = 8 * nt + 2 * qt;
            const int col1 = col0 + 1;
            C[m][nt][0] = (r0 == col0) ? 1.f : 0.f;
            C[m][nt][1] = (r0 == col1) ? 1.f : 0.f;
            C[m][nt][2] = (r1 == col0 && r1 < TT) ? 1.f : 0.f;
            C[m][nt][3] = (r1 == col1 && r1 < TT) ? 1.f : 0.f;
        }
    }

    const int len = lengths[b];
    int steps = len - g * SS;
    steps = (steps < 0) ? 0 : ((steps > SS) ? SS : steps);

    for (int i2 = lane; i2 < steps * TT; i2 += 32) {
        const int i = i2 / TT;
        const int tg = i2 - i * TT;
        xsm[wid][i2] = g_X[((size_t)b * LL + g * SS + i) * TT + tg];
    }
    __syncwarp();

    int Mexp = 0;

    for (int i = 0; i < steps; ++i) {
        float* Ps = &Psm[wid][i & 1][0];

        #pragma unroll
        for (int nt = 0; nt < 3; ++nt) {
            const int col = 8 * nt + 2 * qt;
            *reinterpret_cast<float2*>(&Ps[gr * 28 + col]) =
                make_float2(C[0][nt][0], C[0][nt][1]);
            *reinterpret_cast<float2*>(&Ps[(gr + 8) * 28 + col]) =
                make_float2(C[0][nt][2], C[0][nt][3]);
            *reinterpret_cast<float2*>(&Ps[(16 + gr) * 28 + col]) =
                make_float2(C[1][nt][0], C[1][nt][1]);
        }
        __syncwarp();

        unsigned Bf[3][3][2];
        #pragma unroll
        for (int ks = 0; ks < 3; ++ks)
            #pragma unroll
            for (int nt = 0; nt < 3; ++nt) {
                Bf[ks][nt][0] = f2tf32(Ps[(qt + 8 * ks) * 28 + gr + 8 * nt]);
                Bf[ks][nt][1] = f2tf32(Ps[(qt + 4 + 8 * ks) * 28 + gr + 8 * nt]);
            }

        const float x0 = xsm[wid][i * TT + gr];
        const float x1 = xsm[wid][i * TT + gr + 8];
        const float x2 = xsm[wid][i * TT + 16 + gr];

        float Q[2][3][4];
        #pragma unroll
        for (int m = 0; m < 2; ++m)
            #pragma unroll
            for (int nt = 0; nt < 3; ++nt) {
                Q[m][nt][0] = 0.f; Q[m][nt][1] = 0.f;
                Q[m][nt][2] = 0.f; Q[m][nt][3] = 0.f;
                #pragma unroll
                for (int ks = 0; ks < 3; ++ks)
                    MMA_TF32(Q[m][nt][0], Q[m][nt][1], Q[m][nt][2], Q[m][nt][3],
                             A[m][ks][0], A[m][ks][1], A[m][ks][2], A[m][ks][3],
                             Bf[ks][nt][0], Bf[ks][nt][1]);
            }

        #pragma unroll
        for (int nt = 0; nt < 3; ++nt) {
            C[0][nt][0] = x0 * Q[0][nt][0];  C[0][nt][1] = x0 * Q[0][nt][1];
            C[0][nt][2] = x1 * Q[0][nt][2];  C[0][nt][3] = x1 * Q[0][nt][3];
            C[1][nt][0] = x2 * Q[1][nt][0];  C[1][nt][1] = x2 * Q[1][nt][1];
            C[1][nt][2] = 0.f;               C[1][nt][3] = 0.f;
        }

        if ((i & 3) == 3) {
            float mx = 0.f;
            #pragma unroll
            for (int m = 0; m < 2; ++m)
                #pragma unroll
                for (int nt = 0; nt < 3; ++nt) {
                    mx = fmaxf(mx, fmaxf(C[m][nt][0], C[m][nt][1]));
                    mx = fmaxf(mx, fmaxf(C[m][nt][2], C[m][nt][3]));
                }
            const unsigned mb =
                __reduce_max_sync(0xffffffffu, __float_as_uint(mx));
            const int e  = (int)(mb >> 23);
            const int en = (e == 0) ? 127 : e;
            const float nsc = __uint_as_float((unsigned)(254 - en) << 23);
            #pragma unroll
            for (int m = 0; m < 2; ++m)
                #pragma unroll
                for (int nt = 0; nt < 3; ++nt) {
                    C[m][nt][0] *= nsc; C[m][nt][1] *= nsc;
                    C[m][nt][2] *= nsc; C[m][nt][3] *= nsc;
                }
            Mexp += (en - 127);
        }
    }

    float* Pg = g_P + (size_t)idx * 576;
    #pragma unroll
    for (int nt = 0; nt < 3; ++nt) {
        const int col = 8 * nt + 2 * qt;
        *reinterpret_cast<float2*>(&Pg[gr * TT + col]) =
            make_float2(C[0][nt][0], C[0][nt][1]);
        *reinterpret_cast<float2*>(&Pg[(gr + 8) * TT + col]) =
            make_float2(C[0][nt][2], C[0][nt][3]);
        *reinterpret_cast<float2*>(&Pg[(16 + gr) * TT + col]) =
            make_float2(C[1][nt][0], C[1][nt][1]);
    }
    if (lane == 0) g_M[idx] = Mexp;
}

// ---------------------------------------------------------------------------
// Kernel 3 (Phase B): fold the 32 segment matrices into the alpha vector.
// ---------------------------------------------------------------------------
__global__ __launch_bounds__(32) void combine_kernel(
    const float* __restrict__ trans,
    float*       __restrict__ out)
{
    __shared__ __align__(16) float wbuf[2][32];

    const int lane = threadIdx.x;
    const int b = blockIdx.x;
    const int lanec = (lane < TT) ? lane : (TT - 1);

    const float u = (lane < TT) ? __expf(trans[TAG_STOP * TT + lane]) : 0.f;

    // sum of 32 segment exponents (one per lane)
    int mg = g_M[b * SEG + lane];
    #pragma unroll
    for (int o = 16; o > 0; o >>= 1)
        mg += __shfl_xor_sync(0xffffffffu, mg, o);
    int Mtot = mg;

    float v = (lane == TAG_START) ? 1.f : 0.f;

    const float* Pb = g_P + (size_t)b * SEG * 576;
    float4 R[6];
    #pragma unroll
    for (int i = 0; i < 6; ++i)
        R[i] = *reinterpret_cast<const float4*>(Pb + lanec * TT + i * 4);

    #pragma unroll
    for (int g = 0; g < SEG; ++g) {
        const int p = g & 1;
        wbuf[p][lane] = v;

        const int gn = (g + 1 < SEG) ? (g + 1) : (SEG - 1);
        float4 Rn[6];
        #pragma unroll
        for (int i = 0; i < 6; ++i)
            Rn[i] = *reinterpret_cast<const float4*>(
                Pb + (size_t)gn * 576 + lanec * TT + i * 4);

        __syncwarp();

        const float4* vv = reinterpret_cast<const float4*>(&wbuf[p][0]);
        float a0 = 0.f, a1 = 0.f, a2 = 0.f, a3 = 0.f;
        #pragma unroll
        for (int i = 0; i < 6; ++i) {
            const float4 w4 = vv[i];
            a0 = fmaf(R[i].x, w4.x, a0);
            a1 = fmaf(R[i].y, w4.y, a1);
            a2 = fmaf(R[i].z, w4.z, a2);
            a3 = fmaf(R[i].w, w4.w, a3);
        }
        float vn = (a0 + a1) + (a2 + a3);
        vn = (lane < TT) ? vn : 0.f;

        const unsigned mb = __reduce_max_sync(0xffffffffu, __float_as_uint(vn));
        const int e  = (int)(mb >> 23);
        const int en = (e == 0) ? 127 : e;
        const float nsc = __uint_as_float((unsigned)(254 - en) << 23);
        v = vn * nsc;
        Mtot += (en - 127);

        #pragma unroll
        for (int i = 0; i < 6; ++i) R[i] = Rn[i];
    }

    float term = v * u;
    #pragma unroll
    for (int o = 16; o > 0; o >>= 1)
        term += __shfl_xor_sync(0xffffffffu, term, o);

    if (lane == 0)
        out[b] = __logf(term) + (float)Mtot * 0.69314718055994531f;
}

extern "C" void kernel_launch(void* const* d_in, const int* in_sizes, int n_in,
                              void* d_out, int out_size)
{
    const float* feat   = (const float*)d_in[0];  // [128,512,512]
    const float* Wm     = (const float*)d_in[1];  // [24,512]
    const float* bias   = (const float*)d_in[2];  // [24]
    const float* trans  = (const float*)d_in[3];  // [24,24]
    const int*   lens   = (const int*)d_in[4];    // [128]
    float* out = (float*)d_out;                   // [128]

    emit_kernel<<<512, 256>>>(feat, Wm, bias);
    seg_kernel<<<1024, 128>>>(trans, lens);
    combine_kernel<<<128, 32>>>(trans, out);
}

// round 12
// speedup vs baseline: 1.1281x; 1.1281x over previous
#include <cuda_runtime.h>
#include <cmath>

#define BB 128
#define LL 512
#define HH 512
#define TT 24
#define TAG_START 22
#define TAG_STOP  23
#define SEG 16
#define SS  32            // steps per segment = LL/SEG

// Scratch (device globals; no allocations).
__device__ float g_X[BB * LL * TT];          // exp(emissions)  6.3 MB
__device__ float g_P[BB * SEG * 576];        // segment transport matrices 4.7 MB
__device__ int   g_M[BB * SEG];              // segment exponent offsets

// m16n8k8 tf32 mma (seg_kernel)
#define MMA_TF32(c0,c1,c2,c3,a0,a1,a2,a3,b0,b1) \
  asm("mma.sync.aligned.m16n8k8.row.col.f32.tf32.tf32.f32 " \
      "{%0,%1,%2,%3},{%4,%5,%6,%7},{%8,%9},{%0,%1,%2,%3};" \
      : "+f"(c0),"+f"(c1),"+f"(c2),"+f"(c3) \
      : "r"(a0),"r"(a1),"r"(a2),"r"(a3),"r"(b0),"r"(b1))

// m16n8k16 bf16 mma (emit kernel)
#define MMA_BF16(c0,c1,c2,c3,a0,a1,a2,a3,b0,b1) \
  asm("mma.sync.aligned.m16n8k16.row.col.f32.bf16.bf16.f32 " \
      "{%0,%1,%2,%3},{%4,%5,%6,%7},{%8,%9},{%0,%1,%2,%3};" \
      : "+f"(c0),"+f"(c1),"+f"(c2),"+f"(c3) \
      : "r"(a0),"r"(a1),"r"(a2),"r"(a3),"r"(b0),"r"(b1))

__device__ __forceinline__ unsigned f2tf32(float v) {
    unsigned r;
    asm("cvt.rna.tf32.f32 %0, %1;" : "=r"(r) : "f"(v));
    return r;
}

// pack two floats into bf16x2: low half = lo (smaller k), high half = hi
__device__ __forceinline__ unsigned pk_bf16x2(float lo, float hi) {
    unsigned r;
    asm("cvt.rn.bf16x2.f32 %0, %1, %2;" : "=r"(r) : "f"(hi), "f"(lo));
    return r;
}

#define CP_ASYNC16(dst, src) \
    asm volatile("cp.async.cg.shared.global [%0], [%1], 16;" \
                 :: "r"(dst), "l"(src))
#define CP_COMMIT()  asm volatile("cp.async.commit_group;")
#define CP_WAIT(n)   asm volatile("cp.async.wait_group %0;" :: "n"(n))

// ---------------------------------------------------------------------------
// Kernel 1: emission GEMM + exp via bf16 m16n8k16 tensor cores.
// A streamed gmem->smem with a 4-stage cp.async pipeline (32-col fp32 chunks,
// 3 chunks always in flight); converted to bf16 at fragment-load time.
// W transposed [n][k] bf16 in smem.  CTA: 256 thr / 8 warps / 128 rows.
// ---------------------------------------------------------------------------
#define SK 520    // Wtn row stride in bf16 units (512 used + 8 pad)
#define SAF 36    // A-stage row stride in fp32 units (32 used + 4 pad)
#define CCOL 32   // columns per chunk
#define NCH 16    // chunks (= HH / CCOL)

__global__ void __launch_bounds__(256, 2) emit_kernel(
    const float* __restrict__ feat,
    const float* __restrict__ Wm,
    const float* __restrict__ bias)
{
    __shared__ unsigned short Wtn[TT * SK];   // 24.4 KB  bf16 W^T as [n][k]
    __shared__ float As[4][128 * SAF];        // 73.7 KB  fp32 A 4-stage ring

    const int tid = threadIdx.x;
    const int row8 = tid >> 3;    // 0..31
    const int col4 = tid & 7;     // float4 index within 32-col chunk
    const long rowCTA = (long)blockIdx.x * 128;

    // prologue: start chunks 0..2 streaming immediately
    #pragma unroll
    for (int c = 0; c < 3; ++c) {
        #pragma unroll
        for (int i = 0; i < 4; ++i) {
            const int row = row8 + 32 * i;
            const float* src = feat + (rowCTA + row) * HH + c * CCOL + col4 * 4;
            const unsigned dst = (unsigned)__cvta_generic_to_shared(
                &As[c][row * SAF + col4 * 4]);
            CP_ASYNC16(dst, src);
        }
        CP_COMMIT();
    }

    // stage Wtn[n][k] = bf16(Wm[n*512 + k]) under the async loads
    for (int idx = tid; idx < TT * (HH / 4); idx += 256) {
        const int n  = idx >> 7;
        const int kq = idx & 127;
        const float4 wv = *reinterpret_cast<const float4*>(Wm + n * HH + kq * 4);
        uint2 p;
        p.x = pk_bf16x2(wv.x, wv.y);
        p.y = pk_bf16x2(wv.z, wv.w);
        *reinterpret_cast<uint2*>(&Wtn[n * SK + kq * 4]) = p;
    }

    const int warp = tid >> 5;
    const int lane = tid & 31;
    const int g = lane >> 2;
    const int q = lane & 3;
    const int r0 = warp * 16 + g;

    float c0[3], c1[3], c2[3], c3[3];
    #pragma unroll
    for (int nt = 0; nt < 3; ++nt) { c0[nt]=0.f; c1[nt]=0.f; c2[nt]=0.f; c3[nt]=0.f; }

    #pragma unroll
    for (int c = 0; c < NCH; ++c) {
        CP_WAIT(2);          // chunk c resident (3 groups max in flight)
        __syncthreads();     // make it visible to all warps

        // issue chunk c+3 into ring slot (c+3)&3 (safe: that slot was
        // consumed in iteration c-1, which all warps have passed)
        if (c + 3 < NCH) {
            const int cn = c + 3;
            #pragma unroll
            for (int i = 0; i < 4; ++i) {
                const int row = row8 + 32 * i;
                const float* src =
                    feat + (rowCTA + row) * HH + cn * CCOL + col4 * 4;
                const unsigned dst = (unsigned)__cvta_generic_to_shared(
                    &As[cn & 3][row * SAF + col4 * 4]);
                CP_ASYNC16(dst, src);
            }
        }
        CP_COMMIT();         // commit every iteration (possibly empty group)

        const float* Ac = &As[c & 3][0];
        #pragma unroll
        for (int kk = 0; kk < 2; ++kk) {
            const int kl = kk * 16;
            const float2 f0 = *reinterpret_cast<const float2*>(
                &Ac[r0 * SAF + kl + 2 * q]);
            const float2 f1 = *reinterpret_cast<const float2*>(
                &Ac[(r0 + 8) * SAF + kl + 2 * q]);
            const float2 f2 = *reinterpret_cast<const float2*>(
                &Ac[r0 * SAF + kl + 8 + 2 * q]);
            const float2 f3 = *reinterpret_cast<const float2*>(
                &Ac[(r0 + 8) * SAF + kl + 8 + 2 * q]);
            const unsigned a0 = pk_bf16x2(f0.x, f0.y);
            const unsigned a1 = pk_bf16x2(f1.x, f1.y);
            const unsigned a2 = pk_bf16x2(f2.x, f2.y);
            const unsigned a3 = pk_bf16x2(f3.x, f3.y);

            const int kg = c * CCOL + kl;
            #pragma unroll
            for (int nt = 0; nt < 3; ++nt) {
                const int n = 8 * nt + g;
                const unsigned b0 = *reinterpret_cast<const unsigned*>(
                    &Wtn[n * SK + kg + 2 * q]);
                const unsigned b1 = *reinterpret_cast<const unsigned*>(
                    &Wtn[n * SK + kg + 8 + 2 * q]);
                MMA_BF16(c0[nt], c1[nt], c2[nt], c3[nt],
                         a0, a1, a2, a3, b0, b1);
            }
        }
    }

    // epilogue: add bias, exp, store pairs
    const long rg = rowCTA + r0;
    #pragma unroll
    for (int nt = 0; nt < 3; ++nt) {
        const int col = nt * 8 + 2 * q;
        const float bv0 = __ldg(bias + col);
        const float bv1 = __ldg(bias + col + 1);
        float2 lo = make_float2(__expf(c0[nt] + bv0), __expf(c1[nt] + bv1));
        float2 hi = make_float2(__expf(c2[nt] + bv0), __expf(c3[nt] + bv1));
        *reinterpret_cast<float2*>(g_X + rg * TT + col)       = lo;
        *reinterpret_cast<float2*>(g_X + (rg + 8) * TT + col) = hi;
    }
}

// ---------------------------------------------------------------------------
// Kernel 2 (Phase A): per-segment transport matrices via chained tf32 mma.
// (R10 configuration: SEG=16, SS=32 — measured best)
// ---------------------------------------------------------------------------
__global__ __launch_bounds__(128) void seg_kernel(
    const float* __restrict__ trans,
    const int*   __restrict__ lengths)
{
    __shared__ float Psm[4][2][24 * 28];
    __shared__ float xsm[4][SS * TT];

    const int lane = threadIdx.x & 31;
    const int wid  = threadIdx.x >> 5;
    const int idx  = blockIdx.x * 4 + wid;   // 0..2047
    const int b = idx >> 4;
    const int g = idx & 15;

    const int gr = lane >> 2;
    const int qt = lane & 3;

    unsigned A[2][3][4];
    #pragma unroll
    for (int m = 0; m < 2; ++m) {
        const int r0 = 16 * m + gr;
        const int r1 = r0 + 8;
        #pragma unroll
        for (int ks = 0; ks < 3; ++ks) {
            const int c0 = 8 * ks + qt;
            const int c1 = c0 + 4;
            A[m][ks][0] = (r0 < TT) ? f2tf32(__expf(trans[r0 * TT + c0])) : 0u;
            A[m][ks][1] = (r1 < TT) ? f2tf32(__expf(trans[r1 * TT + c0])) : 0u;
            A[m][ks][2] = (r0 < TT) ? f2tf32(__expf(trans[r0 * TT + c1])) : 0u;
            A[m][ks][3] = (r1 < TT) ? f2tf32(__expf(trans[r1 * TT + c1])) : 0u;
        }
    }

    float C[2][3][4];
    #pragma unroll
    for (int m = 0; m < 2; ++m) {
        const int r0 = 16 * m + gr;
        const int r1 = r0 + 8;
        #pragma unroll
        for (int nt = 0; nt < 3; ++nt) {
            const int col0 = 8 * nt + 2 * qt;
            const int col1 = col0 + 1;
            C[m][nt][0] = (r0 == col0) ? 1.f : 0.f;
            C[m][nt][1] = (r0 == col1) ? 1.f : 0.f;
            C[m][nt][2] = (r1 == col0 && r1 < TT) ? 1.f : 0.f;
            C[m][nt][3] = (r1 == col1 && r1 < TT) ? 1.f : 0.f;
        }
    }

    const int len = lengths[b];
    int steps = len - g * SS;
    steps = (steps < 0) ? 0 : ((steps > SS) ? SS : steps);

    for (int i2 = lane; i2 < steps * TT; i2 += 32) {
        const int i = i2 / TT;
        const int tg = i2 - i * TT;
        xsm[wid][i2] = g_X[((size_t)b * LL + g * SS + i) * TT + tg];
    }
    __syncwarp();

    int Mexp = 0;

    for (int i = 0; i < steps; ++i) {
        float* Ps = &Psm[wid][i & 1][0];

        #pragma unroll
        for (int nt = 0; nt < 3; ++nt) {
            const int col = 8 * nt + 2 * qt;
            *reinterpret_cast<float2*>(&Ps[gr * 28 + col]) =
                make_float2(C[0][nt][0], C[0][nt][1]);
            *reinterpret_cast<float2*>(&Ps[(gr + 8) * 28 + col]) =
                make_float2(C[0][nt][2], C[0][nt][3]);
            *reinterpret_cast<float2*>(&Ps[(16 + gr) * 28 + col]) =
                make_float2(C[1][nt][0], C[1][nt][1]);
        }
        __syncwarp();

        unsigned Bf[3][3][2];
        #pragma unroll
        for (int ks = 0; ks < 3; ++ks)
            #pragma unroll
            for (int nt = 0; nt < 3; ++nt) {
                Bf[ks][nt][0] = f2tf32(Ps[(qt + 8 * ks) * 28 + gr + 8 * nt]);
                Bf[ks][nt][1] = f2tf32(Ps[(qt + 4 + 8 * ks) * 28 + gr + 8 * nt]);
            }

        const float x0 = xsm[wid][i * TT + gr];
        const float x1 = xsm[wid][i * TT + gr + 8];
        const float x2 = xsm[wid][i * TT + 16 + gr];

        float Q[2][3][4];
        #pragma unroll
        for (int m = 0; m < 2; ++m)
            #pragma unroll
            for (int nt = 0; nt < 3; ++nt) {
                Q[m][nt][0] = 0.f; Q[m][nt][1] = 0.f;
                Q[m][nt][2] = 0.f; Q[m][nt][3] = 0.f;
                #pragma unroll
                for (int ks = 0; ks < 3; ++ks)
                    MMA_TF32(Q[m][nt][0], Q[m][nt][1], Q[m][nt][2], Q[m][nt][3],
                             A[m][ks][0], A[m][ks][1], A[m][ks][2], A[m][ks][3],
                             Bf[ks][nt][0], Bf[ks][nt][1]);
            }

        #pragma unroll
        for (int nt = 0; nt < 3; ++nt) {
            C[0][nt][0] = x0 * Q[0][nt][0];  C[0][nt][1] = x0 * Q[0][nt][1];
            C[0][nt][2] = x1 * Q[0][nt][2];  C[0][nt][3] = x1 * Q[0][nt][3];
            C[1][nt][0] = x2 * Q[1][nt][0];  C[1][nt][1] = x2 * Q[1][nt][1];
            C[1][nt][2] = 0.f;               C[1][nt][3] = 0.f;
        }

        if ((i & 3) == 3) {
            float mx = 0.f;
            #pragma unroll
            for (int m = 0; m < 2; ++m)
                #pragma unroll
                for (int nt = 0; nt < 3; ++nt) {
                    mx = fmaxf(mx, fmaxf(C[m][nt][0], C[m][nt][1]));
                    mx = fmaxf(mx, fmaxf(C[m][nt][2], C[m][nt][3]));
                }
            const unsigned mb =
                __reduce_max_sync(0xffffffffu, __float_as_uint(mx));
            const int e  = (int)(mb >> 23);
            const int en = (e == 0) ? 127 : e;
            const float nsc = __uint_as_float((unsigned)(254 - en) << 23);
            #pragma unroll
            for (int m = 0; m < 2; ++m)
                #pragma unroll
                for (int nt = 0; nt < 3; ++nt) {
                    C[m][nt][0] *= nsc; C[m][nt][1] *= nsc;
                    C[m][nt][2] *= nsc; C[m][nt][3] *= nsc;
                }
            Mexp += (en - 127);
        }
    }

    float* Pg = g_P + (size_t)idx * 576;
    #pragma unroll
    for (int nt = 0; nt < 3; ++nt) {
        const int col = 8 * nt + 2 * qt;
        *reinterpret_cast<float2*>(&Pg[gr * TT + col]) =
            make_float2(C[0][nt][0], C[0][nt][1]);
        *reinterpret_cast<float2*>(&Pg[(gr + 8) * TT + col]) =
            make_float2(C[0][nt][2], C[0][nt][3]);
        *reinterpret_cast<float2*>(&Pg[(16 + gr) * TT + col]) =
            make_float2(C[1][nt][0], C[1][nt][1]);
    }
    if (lane == 0) g_M[idx] = Mexp;
}

// ---------------------------------------------------------------------------
// Kernel 3 (Phase B): fold the 16 segment matrices into the alpha vector.
// ---------------------------------------------------------------------------
__global__ __launch_bounds__(32) void combine_kernel(
    const float* __restrict__ trans,
    float*       __restrict__ out)
{
    __shared__ __align__(16) float wbuf[2][32];

    const int lane = threadIdx.x;
    const int b = blockIdx.x;
    const int lanec = (lane < TT) ? lane : (TT - 1);

    const float u = (lane < TT) ? __expf(trans[TAG_STOP * TT + lane]) : 0.f;

    int mg = (lane < SEG) ? g_M[b * SEG + lane] : 0;
    #pragma unroll
    for (int o = 8; o > 0; o >>= 1)
        mg += __shfl_xor_sync(0xffffffffu, mg, o);
    int Mtot = mg;

    float v = (lane == TAG_START) ? 1.f : 0.f;

    const float* Pb = g_P + (size_t)b * SEG * 576;
    float4 R[6];
    #pragma unroll
    for (int i = 0; i < 6; ++i)
        R[i] = *reinterpret_cast<const float4*>(Pb + lanec * TT + i * 4);

    #pragma unroll
    for (int g = 0; g < SEG; ++g) {
        const int p = g & 1;
        wbuf[p][lane] = v;

        const int gn = (g + 1 < SEG) ? (g + 1) : (SEG - 1);
        float4 Rn[6];
        #pragma unroll
        for (int i = 0; i < 6; ++i)
            Rn[i] = *reinterpret_cast<const float4*>(
                Pb + (size_t)gn * 576 + lanec * TT + i * 4);

        __syncwarp();

        const float4* vv = reinterpret_cast<const float4*>(&wbuf[p][0]);
        float a0 = 0.f, a1 = 0.f, a2 = 0.f, a3 = 0.f;
        #pragma unroll
        for (int i = 0; i < 6; ++i) {
            const float4 w4 = vv[i];
            a0 = fmaf(R[i].x, w4.x, a0);
            a1 = fmaf(R[i].y, w4.y, a1);
            a2 = fmaf(R[i].z, w4.z, a2);
            a3 = fmaf(R[i].w, w4.w, a3);
        }
        float vn = (a0 + a1) + (a2 + a3);
        vn = (lane < TT) ? vn : 0.f;

        const unsigned mb = __reduce_max_sync(0xffffffffu, __float_as_uint(vn));
        const int e  = (int)(mb >> 23);
        const int en = (e == 0) ? 127 : e;
        const float nsc = __uint_as_float((unsigned)(254 - en) << 23);
        v = vn * nsc;
        Mtot += (en - 127);

        #pragma unroll
        for (int i = 0; i < 6; ++i) R[i] = Rn[i];
    }

    float term = v * u;
    #pragma unroll
    for (int o = 16; o > 0; o >>= 1)
        term += __shfl_xor_sync(0xffffffffu, term, o);

    if (lane == 0)
        out[b] = __logf(term) + (float)Mtot * 0.69314718055994531f;
}

extern "C" void kernel_launch(void* const* d_in, const int* in_sizes, int n_in,
                              void* d_out, int out_size)
{
    const float* feat   = (const float*)d_in[0];  // [128,512,512]
    const float* Wm     = (const float*)d_in[1];  // [24,512]
    const float* bias   = (const float*)d_in[2];  // [24]
    const float* trans  = (const float*)d_in[3];  // [24,24]
    const int*   lens   = (const int*)d_in[4];    // [128]
    float* out = (float*)d_out;                   // [128]

    emit_kernel<<<512, 256>>>(feat, Wm, bias);
    seg_kernel<<<512, 128>>>(trans, lens);
    combine_kernel<<<128, 32>>>(trans, out);
}

// round 13
// speedup vs baseline: 1.2633x; 1.1199x over previous
#include <cuda_runtime.h>
#include <cmath>

#define BB 128
#define LL 512
#define HH 512
#define TT 24
#define TAG_START 22
#define TAG_STOP  23
#define SEG 16
#define SS  32            // steps per segment = LL/SEG

// Scratch (device globals; no allocations).
__device__ float g_P[BB * SEG * 576];        // segment transport matrices 4.7 MB
__device__ int   g_M[BB * SEG];              // segment exponent offsets

// m16n8k8 tf32 mma (phase 2)
#define MMA_TF32(c0,c1,c2,c3,a0,a1,a2,a3,b0,b1) \
  asm("mma.sync.aligned.m16n8k8.row.col.f32.tf32.tf32.f32 " \
      "{%0,%1,%2,%3},{%4,%5,%6,%7},{%8,%9},{%0,%1,%2,%3};" \
      : "+f"(c0),"+f"(c1),"+f"(c2),"+f"(c3) \
      : "r"(a0),"r"(a1),"r"(a2),"r"(a3),"r"(b0),"r"(b1))

// m16n8k16 bf16 mma (phase 1)
#define MMA_BF16(c0,c1,c2,c3,a0,a1,a2,a3,b0,b1) \
  asm("mma.sync.aligned.m16n8k16.row.col.f32.bf16.bf16.f32 " \
      "{%0,%1,%2,%3},{%4,%5,%6,%7},{%8,%9},{%0,%1,%2,%3};" \
      : "+f"(c0),"+f"(c1),"+f"(c2),"+f"(c3) \
      : "r"(a0),"r"(a1),"r"(a2),"r"(a3),"r"(b0),"r"(b1))

__device__ __forceinline__ unsigned f2tf32(float v) {
    unsigned r;
    asm("cvt.rna.tf32.f32 %0, %1;" : "=r"(r) : "f"(v));
    return r;
}

__device__ __forceinline__ unsigned pk_bf16x2(float lo, float hi) {
    unsigned r;
    asm("cvt.rn.bf16x2.f32 %0, %1, %2;" : "=r"(r) : "f"(hi), "f"(lo));
    return r;
}

#define CP_ASYNC16(dst, src) \
    asm volatile("cp.async.cg.shared.global [%0], [%1], 16;" \
                 :: "r"(dst), "l"(src))
#define CP_COMMIT()  asm volatile("cp.async.commit_group;")
#define CP_WAIT(n)   asm volatile("cp.async.wait_group %0;" :: "n"(n))

#define SK 520    // Wtn row stride in bf16 units
#define SAF 36    // A-stage row stride in fp32 units (32 used + 4 pad)
#define CCOL 32
#define NCH 16

// ---------------------------------------------------------------------------
// Fused kernel: emission GEMM (bf16 mma, cp.async-streamed A) + per-segment
// transport-matrix chain (tf32 mma), one CTA = 4 warps = 4 segments = one
// batch's 128-row l-window.  Emissions never touch gmem (smem xsm).
// Phase-2 Psm aliases the dead cp.async ring.  2 CTAs/SM: one CTA's DRAM
// streaming overlaps the other's tensor phase.
// ---------------------------------------------------------------------------
__global__ void __launch_bounds__(128, 2) fused_kernel(
    const float* __restrict__ feat,
    const float* __restrict__ Wm,
    const float* __restrict__ bias,
    const float* __restrict__ trans,
    const int*   __restrict__ lengths)
{
    __shared__ unsigned short Wtn[TT * SK];   // 24.4 KB bf16 W^T [n][k]
    __shared__ float As[4][128 * SAF];        // 73.7 KB A ring (phase 2: Psm)
    __shared__ float xsm[4][SS * TT];         // 12.3 KB emissions per warp

    const int tid = threadIdx.x;
    const int b    = blockIdx.x >> 2;
    const int quad = blockIdx.x & 3;
    const long rowCTA = (long)b * LL + quad * 128;   // global (b,l) row

    const int row16 = tid >> 3;   // 0..15
    const int col4  = tid & 7;    // float4 index within 32-col chunk

    // ---- phase 1 prologue: start chunks 0..2 streaming
    #pragma unroll
    for (int c = 0; c < 3; ++c) {
        #pragma unroll
        for (int i = 0; i < 8; ++i) {
            const int row = row16 + 16 * i;
            const float* src = feat + (rowCTA + row) * HH + c * CCOL + col4 * 4;
            const unsigned dst = (unsigned)__cvta_generic_to_shared(
                &As[c][row * SAF + col4 * 4]);
            CP_ASYNC16(dst, src);
        }
        CP_COMMIT();
    }

    // stage Wtn under the async loads
    for (int idx = tid; idx < TT * (HH / 4); idx += 128) {
        const int n  = idx >> 7;
        const int kq = idx & 127;
        const float4 wv = *reinterpret_cast<const float4*>(Wm + n * HH + kq * 4);
        uint2 p;
        p.x = pk_bf16x2(wv.x, wv.y);
        p.y = pk_bf16x2(wv.z, wv.w);
        *reinterpret_cast<uint2*>(&Wtn[n * SK + kq * 4]) = p;
    }

    const int lane = tid & 31;
    const int wid  = tid >> 5;       // warp = segment-within-quad
    const int g = lane >> 2;
    const int q = lane & 3;

    float C[2][3][4];
    #pragma unroll
    for (int mm = 0; mm < 2; ++mm)
        #pragma unroll
        for (int nt = 0; nt < 3; ++nt)
            { C[mm][nt][0]=0.f; C[mm][nt][1]=0.f; C[mm][nt][2]=0.f; C[mm][nt][3]=0.f; }

    // ---- phase 1 main loop: 16 chunks of 32 columns
    #pragma unroll
    for (int c = 0; c < NCH; ++c) {
        CP_WAIT(2);
        __syncthreads();

        if (c + 3 < NCH) {
            const int cn = c + 3;
            #pragma unroll
            for (int i = 0; i < 8; ++i) {
                const int row = row16 + 16 * i;
                const float* src =
                    feat + (rowCTA + row) * HH + cn * CCOL + col4 * 4;
                const unsigned dst = (unsigned)__cvta_generic_to_shared(
                    &As[cn & 3][row * SAF + col4 * 4]);
                CP_ASYNC16(dst, src);
            }
        }
        CP_COMMIT();

        const float* Ac = &As[c & 3][0];
        #pragma unroll
        for (int kk = 0; kk < 2; ++kk) {
            const int kl = kk * 16;
            const int kg = c * CCOL + kl;
            #pragma unroll
            for (int mm = 0; mm < 2; ++mm) {
                const int r = wid * 32 + mm * 16 + g;
                const float2 f0 = *reinterpret_cast<const float2*>(
                    &Ac[r * SAF + kl + 2 * q]);
                const float2 f1 = *reinterpret_cast<const float2*>(
                    &Ac[(r + 8) * SAF + kl + 2 * q]);
                const float2 f2 = *reinterpret_cast<const float2*>(
                    &Ac[r * SAF + kl + 8 + 2 * q]);
                const float2 f3 = *reinterpret_cast<const float2*>(
                    &Ac[(r + 8) * SAF + kl + 8 + 2 * q]);
                const unsigned a0 = pk_bf16x2(f0.x, f0.y);
                const unsigned a1 = pk_bf16x2(f1.x, f1.y);
                const unsigned a2 = pk_bf16x2(f2.x, f2.y);
                const unsigned a3 = pk_bf16x2(f3.x, f3.y);
                #pragma unroll
                for (int nt = 0; nt < 3; ++nt) {
                    const int n = 8 * nt + g;
                    const unsigned b0 = *reinterpret_cast<const unsigned*>(
                        &Wtn[n * SK + kg + 2 * q]);
                    const unsigned b1 = *reinterpret_cast<const unsigned*>(
                        &Wtn[n * SK + kg + 8 + 2 * q]);
                    MMA_BF16(C[mm][nt][0], C[mm][nt][1], C[mm][nt][2], C[mm][nt][3],
                             a0, a1, a2, a3, b0, b1);
                }
            }
        }
    }
    CP_WAIT(0);

    // ---- epilogue: bias + exp -> xsm[wid][step*24 + tag]
    #pragma unroll
    for (int mm = 0; mm < 2; ++mm) {
        const int i0 = mm * 16 + g;       // local step index
        #pragma unroll
        for (int nt = 0; nt < 3; ++nt) {
            const int col = nt * 8 + 2 * q;
            const float bv0 = __ldg(bias + col);
            const float bv1 = __ldg(bias + col + 1);
            *reinterpret_cast<float2*>(&xsm[wid][i0 * TT + col]) =
                make_float2(__expf(C[mm][nt][0] + bv0),
                            __expf(C[mm][nt][1] + bv1));
            *reinterpret_cast<float2*>(&xsm[wid][(i0 + 8) * TT + col]) =
                make_float2(__expf(C[mm][nt][2] + bv0),
                            __expf(C[mm][nt][3] + bv1));
        }
    }
    __syncthreads();   // ring dead, xsm complete -> phase 2 may reuse As

    // ================= phase 2: segment transport chain =================
    const int gseg = quad * 4 + wid;          // segment 0..15
    const int len = lengths[b];
    int steps = len - gseg * SS;
    steps = (steps < 0) ? 0 : ((steps > SS) ? SS : steps);

    // E A-fragments (tf32)
    unsigned A[2][3][4];
    #pragma unroll
    for (int m = 0; m < 2; ++m) {
        const int r0 = 16 * m + g;
        const int r1 = r0 + 8;
        #pragma unroll
        for (int ks = 0; ks < 3; ++ks) {
            const int c0 = 8 * ks + q;
            const int c1 = c0 + 4;
            A[m][ks][0] = (r0 < TT) ? f2tf32(__expf(trans[r0 * TT + c0])) : 0u;
            A[m][ks][1] = (r1 < TT) ? f2tf32(__expf(trans[r1 * TT + c0])) : 0u;
            A[m][ks][2] = (r0 < TT) ? f2tf32(__expf(trans[r0 * TT + c1])) : 0u;
            A[m][ks][3] = (r1 < TT) ? f2tf32(__expf(trans[r1 * TT + c1])) : 0u;
        }
    }

    // C = identity
    #pragma unroll
    for (int m = 0; m < 2; ++m) {
        const int r0 = 16 * m + g;
        const int r1 = r0 + 8;
        #pragma unroll
        for (int nt = 0; nt < 3; ++nt) {
            const int col0 = 8 * nt + 2 * q;
            const int col1 = col0 + 1;
            C[m][nt][0] = (r0 == col0) ? 1.f : 0.f;
            C[m][nt][1] = (r0 == col1) ? 1.f : 0.f;
            C[m][nt][2] = (r1 == col0 && r1 < TT) ? 1.f : 0.f;
            C[m][nt][3] = (r1 == col1 && r1 < TT) ? 1.f : 0.f;
        }
    }

    // Psm aliases the ring: 2 buffers of 24x28 floats per warp
    float* Psm = reinterpret_cast<float*>(&As[0][0]) + wid * 2 * 672;

    int Mexp = 0;

    for (int i = 0; i < steps; ++i) {
        float* Ps = Psm + (i & 1) * 672;

        #pragma unroll
        for (int nt = 0; nt < 3; ++nt) {
            const int col = 8 * nt + 2 * q;
            *reinterpret_cast<float2*>(&Ps[g * 28 + col]) =
                make_float2(C[0][nt][0], C[0][nt][1]);
            *reinterpret_cast<float2*>(&Ps[(g + 8) * 28 + col]) =
                make_float2(C[0][nt][2], C[0][nt][3]);
            *reinterpret_cast<float2*>(&Ps[(16 + g) * 28 + col]) =
                make_float2(C[1][nt][0], C[1][nt][1]);
        }
        __syncwarp();

        unsigned Bf[3][3][2];
        #pragma unroll
        for (int ks = 0; ks < 3; ++ks)
            #pragma unroll
            for (int nt = 0; nt < 3; ++nt) {
                Bf[ks][nt][0] = f2tf32(Ps[(q + 8 * ks) * 28 + g + 8 * nt]);
                Bf[ks][nt][1] = f2tf32(Ps[(q + 4 + 8 * ks) * 28 + g + 8 * nt]);
            }

        const float x0 = xsm[wid][i * TT + g];
        const float x1 = xsm[wid][i * TT + g + 8];
        const float x2 = xsm[wid][i * TT + 16 + g];

        float Q[2][3][4];
        #pragma unroll
        for (int m = 0; m < 2; ++m)
            #pragma unroll
            for (int nt = 0; nt < 3; ++nt) {
                Q[m][nt][0] = 0.f; Q[m][nt][1] = 0.f;
                Q[m][nt][2] = 0.f; Q[m][nt][3] = 0.f;
                #pragma unroll
                for (int ks = 0; ks < 3; ++ks)
                    MMA_TF32(Q[m][nt][0], Q[m][nt][1], Q[m][nt][2], Q[m][nt][3],
                             A[m][ks][0], A[m][ks][1], A[m][ks][2], A[m][ks][3],
                             Bf[ks][nt][0], Bf[ks][nt][1]);
            }

        #pragma unroll
        for (int nt = 0; nt < 3; ++nt) {
            C[0][nt][0] = x0 * Q[0][nt][0];  C[0][nt][1] = x0 * Q[0][nt][1];
            C[0][nt][2] = x1 * Q[0][nt][2];  C[0][nt][3] = x1 * Q[0][nt][3];
            C[1][nt][0] = x2 * Q[1][nt][0];  C[1][nt][1] = x2 * Q[1][nt][1];
            C[1][nt][2] = 0.f;               C[1][nt][3] = 0.f;
        }

        if ((i & 3) == 3) {
            float mx = 0.f;
            #pragma unroll
            for (int m = 0; m < 2; ++m)
                #pragma unroll
                for (int nt = 0; nt < 3; ++nt) {
                    mx = fmaxf(mx, fmaxf(C[m][nt][0], C[m][nt][1]));
                    mx = fmaxf(mx, fmaxf(C[m][nt][2], C[m][nt][3]));
                }
            const unsigned mb =
                __reduce_max_sync(0xffffffffu, __float_as_uint(mx));
            const int e  = (int)(mb >> 23);
            const int en = (e == 0) ? 127 : e;
            const float nsc = __uint_as_float((unsigned)(254 - en) << 23);
            #pragma unroll
            for (int m = 0; m < 2; ++m)
                #pragma unroll
                for (int nt = 0; nt < 3; ++nt) {
                    C[m][nt][0] *= nsc; C[m][nt][1] *= nsc;
                    C[m][nt][2] *= nsc; C[m][nt][3] *= nsc;
                }
            Mexp += (en - 127);
        }
    }

    // store P_g and Mexp
    const int idx = b * SEG + gseg;
    float* Pg = g_P + (size_t)idx * 576;
    #pragma unroll
    for (int nt = 0; nt < 3; ++nt) {
        const int col = 8 * nt + 2 * q;
        *reinterpret_cast<float2*>(&Pg[g * TT + col]) =
            make_float2(C[0][nt][0], C[0][nt][1]);
        *reinterpret_cast<float2*>(&Pg[(g + 8) * TT + col]) =
            make_float2(C[0][nt][2], C[0][nt][3]);
        *reinterpret_cast<float2*>(&Pg[(16 + g) * TT + col]) =
            make_float2(C[1][nt][0], C[1][nt][1]);
    }
    if (lane == 0) g_M[idx] = Mexp;
}

// ---------------------------------------------------------------------------
// Combine: fold the 16 segment matrices into the alpha vector (unchanged).
// ---------------------------------------------------------------------------
__global__ __launch_bounds__(32) void combine_kernel(
    const float* __restrict__ trans,
    float*       __restrict__ out)
{
    __shared__ __align__(16) float wbuf[2][32];

    const int lane = threadIdx.x;
    const int b = blockIdx.x;
    const int lanec = (lane < TT) ? lane : (TT - 1);

    const float u = (lane < TT) ? __expf(trans[TAG_STOP * TT + lane]) : 0.f;

    int mg = (lane < SEG) ? g_M[b * SEG + lane] : 0;
    #pragma unroll
    for (int o = 8; o > 0; o >>= 1)
        mg += __shfl_xor_sync(0xffffffffu, mg, o);
    int Mtot = mg;

    float v = (lane == TAG_START) ? 1.f : 0.f;

    const float* Pb = g_P + (size_t)b * SEG * 576;
    float4 R[6];
    #pragma unroll
    for (int i = 0; i < 6; ++i)
        R[i] = *reinterpret_cast<const float4*>(Pb + lanec * TT + i * 4);

    #pragma unroll
    for (int g = 0; g < SEG; ++g) {
        const int p = g & 1;
        wbuf[p][lane] = v;

        const int gn = (g + 1 < SEG) ? (g + 1) : (SEG - 1);
        float4 Rn[6];
        #pragma unroll
        for (int i = 0; i < 6; ++i)
            Rn[i] = *reinterpret_cast<const float4*>(
                Pb + (size_t)gn * 576 + lanec * TT + i * 4);

        __syncwarp();

        const float4* vv = reinterpret_cast<const float4*>(&wbuf[p][0]);
        float a0 = 0.f, a1 = 0.f, a2 = 0.f, a3 = 0.f;
        #pragma unroll
        for (int i = 0; i < 6; ++i) {
            const float4 w4 = vv[i];
            a0 = fmaf(R[i].x, w4.x, a0);
            a1 = fmaf(R[i].y, w4.y, a1);
            a2 = fmaf(R[i].z, w4.z, a2);
            a3 = fmaf(R[i].w, w4.w, a3);
        }
        float vn = (a0 + a1) + (a2 + a3);
        vn = (lane < TT) ? vn : 0.f;

        const unsigned mb = __reduce_max_sync(0xffffffffu, __float_as_uint(vn));
        const int e  = (int)(mb >> 23);
        const int en = (e == 0) ? 127 : e;
        const float nsc = __uint_as_float((unsigned)(254 - en) << 23);
        v = vn * nsc;
        Mtot += (en - 127);

        #pragma unroll
        for (int i = 0; i < 6; ++i) R[i] = Rn[i];
    }

    float term = v * u;
    #pragma unroll
    for (int o = 16; o > 0; o >>= 1)
        term += __shfl_xor_sync(0xffffffffu, term, o);

    if (lane == 0)
        out[b] = __logf(term) + (float)Mtot * 0.69314718055994531f;
}

extern "C" void kernel_launch(void* const* d_in, const int* in_sizes, int n_in,
                              void* d_out, int out_size)
{
    const float* feat   = (const float*)d_in[0];  // [128,512,512]
    const float* Wm     = (const float*)d_in[1];  // [24,512]
    const float* bias   = (const float*)d_in[2];  // [24]
    const float* trans  = (const float*)d_in[3];  // [24,24]
    const int*   lens   = (const int*)d_in[4];    // [128]
    float* out = (float*)d_out;                   // [128]

    fused_kernel<<<512, 128>>>(feat, Wm, bias, trans, lens);
    combine_kernel<<<128, 32>>>(trans, out);
}